// round 16
// baseline (speedup 1.0000x reference)
#include <cuda_runtime.h>

#define BB 8
#define TT 4096
#define DD 256
#define HH 256
#define G4 1024   // 4*H
#define CLUS 8
#define NTHR 512
#define NT1 1152  // chunk-1 time prefix (must be multiple of 128)

// 128 MB scratch, T-INDEXED: g_xWi[b][t][col] = (x@Wi + b)[b][src(t)][col]
__device__ float    g_xWi[BB * TT * G4];
__device__ unsigned g_flag;    // chunk2 completion flag
__device__ unsigned g_count;   // chunk2 CTA completion counter

// ---------------------------------------------------------------------------
__global__ void init_kernel() {
    if (threadIdx.x == 0) { g_flag = 0u; g_count = 0u; }
}

// ---------------------------------------------------------------------------
// GEMM over a time range [t0, t0 + 128*tilesPerB):
//   out[b][t] = x[b][src(t)] @ Wi + bias,  src(t) = (TT-1-t+L_b) & (TT-1)
// BM=128 (t-tile), BN=64, BK=16, 256 threads, 8x4 register tile.
// flag_total > 0 => participate in the chunk2 completion protocol.
// ---------------------------------------------------------------------------
__global__ void __launch_bounds__(256) gemm_t_kernel(
    const float* __restrict__ x, const float* __restrict__ Wi,
    const float* __restrict__ bias, const int* __restrict__ seqlen,
    int t0, int flag_total) {
    __shared__ float As[16][132];
    __shared__ float Bs[16][64];

    int tid = threadIdx.x;
    int tPerB = gridDim.y / BB;
    int b  = blockIdx.y / tPerB;
    int tb = blockIdx.y % tPerB;
    int bn = blockIdx.x;
    const int t_base = t0 + tb * 128;
    const int L = seqlen[b];

    const float* xb   = x + (size_t)b * TT * DD;
    const float* Bblk = Wi + bn * 64;

    int ty = tid >> 4;
    int tx = tid & 15;

    float acc[8][4];
#pragma unroll
    for (int i = 0; i < 8; i++)
#pragma unroll
        for (int j = 0; j < 4; j++) acc[i][j] = 0.f;

    for (int k0 = 0; k0 < DD; k0 += 16) {
#pragma unroll
        for (int i = 0; i < 2; i++) {
            int f4  = tid * 2 + i;
            int row = f4 >> 2;                 // local t offset 0..127
            int kq  = (f4 & 3) * 4;
            int t    = t_base + row;
            int trow = (TT - 1 - t + L) & (TT - 1);
            float4 v = *(const float4*)(xb + (size_t)trow * DD + k0 + kq);
            As[kq + 0][row] = v.x;
            As[kq + 1][row] = v.y;
            As[kq + 2][row] = v.z;
            As[kq + 3][row] = v.w;
        }
        {
            int kk = tid >> 4;
            int nc = (tid & 15) * 4;
            *(float4*)&Bs[kk][nc] =
                *(const float4*)(Bblk + (size_t)(k0 + kk) * G4 + nc);
        }
        __syncthreads();

#pragma unroll
        for (int kk = 0; kk < 16; kk++) {
            float a[8], bb[4];
            *(float4*)(a)     = *(float4*)&As[kk][ty * 8];
            *(float4*)(a + 4) = *(float4*)&As[kk][ty * 8 + 4];
            *(float4*)(bb)    = *(float4*)&Bs[kk][tx * 4];
#pragma unroll
            for (int i = 0; i < 8; i++)
#pragma unroll
                for (int j = 0; j < 4; j++) acc[i][j] += a[i] * bb[j];
        }
        __syncthreads();
    }

    int col = bn * 64 + tx * 4;
    float4 bv = *(const float4*)(bias + col);
#pragma unroll
    for (int i = 0; i < 8; i++) {
        int trow_out = t_base + ty * 8 + i;
        float4 o;
        o.x = acc[i][0] + bv.x;
        o.y = acc[i][1] + bv.y;
        o.z = acc[i][2] + bv.z;
        o.w = acc[i][3] + bv.w;
        *(float4*)(g_xWi + ((size_t)b * TT + trow_out) * G4 + col) = o;
    }

    // chunk2 completion protocol: last CTA releases the flag
    if (flag_total) {
        __syncthreads();
        if (tid == 0) {
            __threadfence();
            unsigned v = atomicAdd(&g_count, 1u);
            if (v + 1u == (unsigned)flag_total)
                asm volatile("st.release.gpu.global.u32 [%0], %1;"
                             :: "l"(&g_flag), "r"(1u) : "memory");
        }
    }
}

// ---------------------------------------------------------------------------
// Recurrent kernel (R15 structure): 1 cluster (8 CTAs x 512) per batch.
// Lane owns d-chunk of 8 (Wh in regs, packed f32x2); full-split butterfly
// leaves column q=(l>>2)&7's sum on lane l; each lane LDGs its OWN column's
// xWi (t-indexed -> sequential; quad-mates broadcast from one address) and
// applies its column's activation pre-gather; 4 shfl.idx gathers give each
// half its activated gates; all lanes redundantly update c_state/nh;
// lanes 0-7 do ONE st.shared::cluster.v2.f32 per peer. HW cluster barrier,
// split arrive/wait with y-store + xc swap inside the window.
// Single acquire-spin at t==NT1-1 gates entry into chunk2's data.
// No DSMEM store after the final barrier (peer-exit race).
// ---------------------------------------------------------------------------
__global__ void __launch_bounds__(NTHR, 1) __cluster_dims__(CLUS, 1, 1)
rnn_kernel(const float* __restrict__ Wh,
           const int* __restrict__ seqlen,
           float* __restrict__ y) {
    __shared__ float h_s[2][HH];

    const int b = blockIdx.x / CLUS;
    const int r = blockIdx.x % CLUS;
    const int w = threadIdx.x >> 5;
    const int l = threadIdx.x & 31;
    const int k0 = r * 32 + 2 * w;

    // ---- preload Wh slice as packed f32x2 pairs over d ----
    unsigned long long wh2[8][4];
#pragma unroll
    for (int j = 0; j < 8; j++) {
        int col = (j < 4) ? (k0 + 256 * j) : (k0 + 1 + 256 * (j - 4));
#pragma unroll
        for (int dd = 0; dd < 4; dd++) {
            int d = l * 8 + dd * 2;
            float lo = Wh[(size_t)d * G4 + col];
            float hi = Wh[(size_t)(d + 1) * G4 + col];
            asm("mov.b64 %0, {%1, %2};" : "=l"(wh2[j][dd]) : "f"(lo), "f"(hi));
        }
    }

    for (int i = threadIdx.x; i < HH; i += NTHR) h_s[0][i] = 0.f;
    __syncthreads();
    asm volatile("barrier.cluster.arrive.aligned;" ::: "memory");
    asm volatile("barrier.cluster.wait.aligned;"   ::: "memory");

    const int L = seqlen[b];
    const float* xWib = g_xWi + (size_t)b * TT * G4;
    float*       yb   = y + (size_t)b * TT * HH;

    const int myk = k0 + ((l >> 4) & 1);
    float c_state = 0.f;

    unsigned int hs_addr;
    asm("{ .reg .u64 t; cvta.to.shared.u64 t, %1; cvt.u32.u64 %0, t; }"
        : "=r"(hs_addr) : "l"((void*)h_s));
    unsigned int st_peer;
    {
        unsigned int slot = hs_addr + (unsigned)k0 * 4u;   // 8B aligned
        asm("mapa.shared::cluster.u32 %0, %1, %2;"
            : "=r"(st_peer) : "r"(slot), "r"(l & 7));
    }

    // this lane's OWN gate column (quad q) — 4 lanes share one address
    const int q     = (l >> 2) & 7;
    const int mycol = (q < 4) ? (k0 + 256 * q) : (k0 + 1 + 256 * (q - 4));

    // preload xWi for t=0 (t-indexed, sequential)
    float xc = xWib[mycol];

    const int  base   = l & 16;
    const bool is_g   = (q == 2 || q == 6);   // candidate gate -> tanh
    const bool ystore = ((l & 15) == 0);

    for (int t = 0; t < TT; t++) {
        // gate entry into chunk2's data (single coarse flag)
        if (t == NT1 - 1) {
            if (threadIdx.x == 0) {
                unsigned f;
                do {
                    asm volatile("ld.acquire.gpu.global.u32 %0, [%1];"
                                 : "=r"(f) : "l"(&g_flag));
                } while (!f);
            }
            __syncthreads();
        }

        // prefetch next step's xWi (all lanes, own column, sequential t)
        float xn = 0.f;
        if (t + 1 < TT) xn = xWib[(size_t)(t + 1) * G4 + mycol];

        const unsigned long long* hp =
            (const unsigned long long*)&h_s[t & 1][l * 8];
        unsigned long long h2[4];
        h2[0] = hp[0]; h2[1] = hp[1]; h2[2] = hp[2]; h2[3] = hp[3];

        unsigned long long acc[8];
#pragma unroll
        for (int j = 0; j < 8; j++) acc[j] = 0ull;
#pragma unroll
        for (int dd = 0; dd < 4; dd++)
#pragma unroll
            for (int j = 0; j < 8; j++)
                asm("fma.rn.f32x2 %0, %1, %2, %0;"
                    : "+l"(acc[j]) : "l"(h2[dd]), "l"(wh2[j][dd]));

        float ps[8];
#pragma unroll
        for (int j = 0; j < 8; j++) {
            float lo, hi;
            asm("mov.b64 {%0, %1}, %2;" : "=f"(lo), "=f"(hi) : "l"(acc[j]));
            ps[j] = lo + hi;
        }

        // full-split butterfly: 16 SHFL, 5 levels -> quad q holds column q
        float u0, u1, u2, u3;
        {
            float a0 = __shfl_xor_sync(0xffffffffu, ps[0], 16);
            float a4 = __shfl_xor_sync(0xffffffffu, ps[4], 16);
            float a1 = __shfl_xor_sync(0xffffffffu, ps[1], 16);
            float a5 = __shfl_xor_sync(0xffffffffu, ps[5], 16);
            float a2 = __shfl_xor_sync(0xffffffffu, ps[2], 16);
            float a6 = __shfl_xor_sync(0xffffffffu, ps[6], 16);
            float a3 = __shfl_xor_sync(0xffffffffu, ps[3], 16);
            float a7 = __shfl_xor_sync(0xffffffffu, ps[7], 16);
            bool hi = (l & 16);
            u0 = hi ? (ps[4] + a4) : (ps[0] + a0);
            u1 = hi ? (ps[5] + a5) : (ps[1] + a1);
            u2 = hi ? (ps[6] + a6) : (ps[2] + a2);
            u3 = hi ? (ps[7] + a7) : (ps[3] + a3);
        }
        float t0, t1;
        {
            float a0 = __shfl_xor_sync(0xffffffffu, u0, 8);
            float a2 = __shfl_xor_sync(0xffffffffu, u2, 8);
            float a1 = __shfl_xor_sync(0xffffffffu, u1, 8);
            float a3 = __shfl_xor_sync(0xffffffffu, u3, 8);
            bool hi = (l & 8);
            t0 = hi ? (u2 + a2) : (u0 + a0);
            t1 = hi ? (u3 + a3) : (u1 + a1);
        }
        float s;
        {
            float a0 = __shfl_xor_sync(0xffffffffu, t0, 4);
            float a1 = __shfl_xor_sync(0xffffffffu, t1, 4);
            s = (l & 4) ? (t1 + a1) : (t0 + a0);
        }
        s += __shfl_xor_sync(0xffffffffu, s, 2);
        s += __shfl_xor_sync(0xffffffffu, s, 1);

        // add own column's xWi pre-activation (no shfl needed)
        s += xc;

        // distributed activation of MY column
        float arg = is_g ? (2.f * s) : s;
        float e   = __expf(-arg);
        float sg  = __fdividef(1.f, 1.f + e);
        float act = is_g ? fmaf(2.f, sg, -1.f) : sg;

        // gather activated gates of my half's h-index
        float g0 = __shfl_sync(0xffffffffu, act, base + 0);
        float g1 = __shfl_sync(0xffffffffu, act, base + 4);
        float g2 = __shfl_sync(0xffffffffu, act, base + 8);
        float g3 = __shfl_sync(0xffffffffu, act, base + 12);

        // all lanes: LSTM cell update for their half (redundant, branch-free)
        c_state = fmaf(g1, c_state, g0 * g2);
        float e2 = __expf(-2.f * c_state);
        float tc = fmaf(2.f, __fdividef(1.f, 1.f + e2), -1.f);
        float nh = g3 * tc;

        float nho = __shfl_sync(0xffffffffu, nh, l | 16);

        if (t < TT - 1 && l < 8) {
            unsigned int dst =
                st_peer + (((t + 1) & 1) ? (unsigned)HH * 4u : 0u);
            asm volatile("st.shared::cluster.v2.f32 [%0], {%1, %2};"
                         :: "r"(dst), "f"(nh), "f"(nho) : "memory");
        }

        if (t < TT - 1)
            asm volatile("barrier.cluster.arrive.aligned;" ::: "memory");

        if (ystore) {
            const int src = (TT - 1 - t + L) & (TT - 1);
            yb[(size_t)src * HH + myk] = nh;
        }
        xc = xn;

        if (t < TT - 1)
            asm volatile("barrier.cluster.wait.aligned;" ::: "memory");
    }
}

// ---------------------------------------------------------------------------
extern "C" void kernel_launch(void* const* d_in, const int* in_sizes, int n_in,
                              void* d_out, int out_size) {
    const float* x    = (const float*)d_in[0];
    const float* Wi   = (const float*)d_in[1];
    const float* Wh   = (const float*)d_in[2];
    const float* bias = (const float*)d_in[3];
    const int*   seql = (const int*)d_in[4];
    float*       y    = (float*)d_out;

    // statics created on the (uncaptured) correctness call; reused in capture
    static cudaStream_t s2 = 0;
    static cudaEvent_t  e1 = 0, e2 = 0;
    if (!s2) {
        int lo = 0, hi = 0;
        cudaDeviceGetStreamPriorityRange(&lo, &hi);
        cudaStreamCreateWithPriority(&s2, cudaStreamNonBlocking, lo);
        cudaEventCreateWithFlags(&e1, cudaEventDisableTiming);
        cudaEventCreateWithFlags(&e2, cudaEventDisableTiming);
    }

    const int nT2 = TT - NT1;
    const int flag_total = 16 * BB * nT2 / 128;   // chunk2 CTA count

    init_kernel<<<1, 32>>>();
    cudaEventRecord(e1, 0);
    cudaStreamWaitEvent(s2, e1, 0);
    // chunk2 (low priority, concurrent with rnn on the free SMs)
    gemm_t_kernel<<<dim3(16, BB * nT2 / 128), 256, 0, s2>>>(
        x, Wi, bias, seql, NT1, flag_total);
    cudaEventRecord(e2, s2);
    // chunk1 (stream 0, before rnn)
    gemm_t_kernel<<<dim3(16, BB * NT1 / 128), 256>>>(
        x, Wi, bias, seql, 0, 0);
    rnn_kernel<<<BB * CLUS, NTHR>>>(Wh, seql, y);
    cudaStreamWaitEvent(0, e2, 0);   // join fork for capture completeness
}

// round 17
// speedup vs baseline: 1.3664x; 1.3664x over previous
#include <cuda_runtime.h>

#define BB 8
#define TT 4096
#define DD 256
#define HH 256
#define G4 1024   // 4*H
#define CLUS 8
#define NTHR 512

// 128 MB scratch for x@Wi+b, [B*T, 4H]
__device__ float g_xWi[BB * TT * G4];

// ---------------------------------------------------------------------------
// GEMM: g_xWi = x[B*T, D] @ Wi[D, 4H] + b
// BM=128, BN=128, BK=16, 256 threads, 8x8 register tile (cols split
// tx*4 / 64+tx*4 for conflict-free Bs reads). ~16 FMA per LDS.128.
// ---------------------------------------------------------------------------
__global__ void __launch_bounds__(256) gemm_kernel(const float* __restrict__ x,
                                                   const float* __restrict__ Wi,
                                                   const float* __restrict__ bias) {
    __shared__ float As[16][132];   // [k][m], padded
    __shared__ float Bs[16][128];   // [k][n]

    int tid = threadIdx.x;
    int bm = blockIdx.y, bn = blockIdx.x;
    const float* Ablk = x + (size_t)bm * 128 * DD;
    const float* Bblk = Wi + bn * 128;

    int ty = tid >> 4;         // 0..15 -> 8 rows each
    int tx = tid & 15;         // 0..15 -> cols tx*4.. and 64+tx*4..

    float acc[8][8];
#pragma unroll
    for (int i = 0; i < 8; i++)
#pragma unroll
        for (int j = 0; j < 8; j++) acc[i][j] = 0.f;

    for (int k0 = 0; k0 < DD; k0 += 16) {
        // A tile: 128x16 = 512 float4, 2/thread, stored transposed
#pragma unroll
        for (int i = 0; i < 2; i++) {
            int f4  = tid * 2 + i;
            int row = f4 >> 2;
            int kq  = (f4 & 3) * 4;
            float4 v = *(const float4*)(Ablk + (size_t)row * DD + k0 + kq);
            As[kq + 0][row] = v.x;
            As[kq + 1][row] = v.y;
            As[kq + 2][row] = v.z;
            As[kq + 3][row] = v.w;
        }
        // B tile: 16x128 = 512 float4, 2/thread
#pragma unroll
        for (int i = 0; i < 2; i++) {
            int idx = tid * 2 + i;
            int kk  = idx >> 5;
            int nc  = (idx & 31) * 4;
            *(float4*)&Bs[kk][nc] =
                *(const float4*)(Bblk + (size_t)(k0 + kk) * G4 + nc);
        }
        __syncthreads();

#pragma unroll
        for (int kk = 0; kk < 16; kk++) {
            float a[8], bv[8];
            *(float4*)(a)      = *(float4*)&As[kk][ty * 8];
            *(float4*)(a + 4)  = *(float4*)&As[kk][ty * 8 + 4];
            *(float4*)(bv)     = *(float4*)&Bs[kk][tx * 4];
            *(float4*)(bv + 4) = *(float4*)&Bs[kk][64 + tx * 4];
#pragma unroll
            for (int i = 0; i < 8; i++)
#pragma unroll
                for (int j = 0; j < 8; j++) acc[i][j] += a[i] * bv[j];
        }
        __syncthreads();
    }

    int col1 = bn * 128 + tx * 4;
    int col2 = col1 + 64;
    float4 b1 = *(const float4*)(bias + col1);
    float4 b2 = *(const float4*)(bias + col2);
#pragma unroll
    for (int i = 0; i < 8; i++) {
        int row = bm * 128 + ty * 8 + i;
        float4 o1, o2;
        o1.x = acc[i][0] + b1.x;
        o1.y = acc[i][1] + b1.y;
        o1.z = acc[i][2] + b1.z;
        o1.w = acc[i][3] + b1.w;
        o2.x = acc[i][4] + b2.x;
        o2.y = acc[i][5] + b2.y;
        o2.z = acc[i][6] + b2.z;
        o2.w = acc[i][7] + b2.w;
        *(float4*)(g_xWi + (size_t)row * G4 + col1) = o1;
        *(float4*)(g_xWi + (size_t)row * G4 + col2) = o2;
    }
}

// ---------------------------------------------------------------------------
// Recurrent kernel (R15 winner, byte-identical): 1 cluster (8 CTAs x 512)
// per batch; grid = 64 CTAs. Warp w handles the 8 gate columns of
// k0=32r+2w, k0+1; lane owns a d-chunk of 8 (Wh in regs, packed f32x2).
// Fully distributed, predication-free gate phase:
//  - full-split butterfly leaves column q=(l>>2)&7's sum on lane l
//  - each lane applies ITS column's activation pre-gather
//  - 4 shfl.idx gathers; ALL lanes redundantly update c_state/nh
//  - lanes 0-7: ONE st.shared::cluster.v2.f32 per peer
//  - split cluster arrive/wait, y store + xc swap inside the window
// No DSMEM store after the final barrier (peer-exit race).
// ---------------------------------------------------------------------------
__global__ void __launch_bounds__(NTHR, 1) __cluster_dims__(CLUS, 1, 1)
rnn_kernel(const float* __restrict__ Wh,
           const int* __restrict__ seqlen,
           float* __restrict__ y) {
    __shared__ float h_s[2][HH];

    const int b = blockIdx.x / CLUS;
    const int r = blockIdx.x % CLUS;
    const int w = threadIdx.x >> 5;
    const int l = threadIdx.x & 31;
    const int k0 = r * 32 + 2 * w;

    // ---- preload Wh slice as packed f32x2 pairs over d ----
    unsigned long long wh2[8][4];
#pragma unroll
    for (int j = 0; j < 8; j++) {
        int col = (j < 4) ? (k0 + 256 * j) : (k0 + 1 + 256 * (j - 4));
#pragma unroll
        for (int dd = 0; dd < 4; dd++) {
            int d = l * 8 + dd * 2;
            float lo = Wh[(size_t)d * G4 + col];
            float hi = Wh[(size_t)(d + 1) * G4 + col];
            asm("mov.b64 %0, {%1, %2};" : "=l"(wh2[j][dd]) : "f"(lo), "f"(hi));
        }
    }

    // ---- zero initial hidden state (buffer 0) ----
    for (int i = threadIdx.x; i < HH; i += NTHR) h_s[0][i] = 0.f;
    __syncthreads();
    asm volatile("barrier.cluster.arrive.aligned;" ::: "memory");
    asm volatile("barrier.cluster.wait.aligned;"   ::: "memory");

    const int L = seqlen[b];
    const float* xWib = g_xWi + (size_t)b * TT * G4;
    float*       yb   = y + (size_t)b * TT * HH;

    // lanes 0-15 track k0's c_state, lanes 16-31 track k0+1's (redundant)
    const int myk = k0 + ((l >> 4) & 1);
    float c_state = 0.f;

    // DSMEM peer v2-store address: lane p<8 stores (k0,k0+1) to peer p
    unsigned int hs_addr;
    asm("{ .reg .u64 t; cvta.to.shared.u64 t, %1; cvt.u32.u64 %0, t; }"
        : "=r"(hs_addr) : "l"((void*)h_s));
    unsigned int st_peer;
    {
        unsigned int slot = hs_addr + (unsigned)k0 * 4u;   // 8B aligned
        asm("mapa.shared::cluster.u32 %0, %1, %2;"
            : "=r"(st_peer) : "r"(slot), "r"(l & 7));
    }

    // xWi column for loader lanes 0..7 (column c of this warp)
    const int c    = l & 7;
    const int gcol = (c < 4) ? (k0 + 256 * c) : (k0 + 1 + 256 * (c - 4));

    // preload xWi for t=0 (lanes 0..7: one LDG per warp)
    float xc = 0.f;
    if (l < 8) {
        int src0 = (TT - 1 + L) & (TT - 1);
        xc = xWib[(size_t)src0 * G4 + gcol];
    }

    const int  base   = l & 16;            // gather base for this half
    const int  gidx   = (l >> 2) & 3;      // gate index of my column
    const bool is_g   = (gidx == 2);       // candidate gate -> tanh
    const bool ystore = ((l & 15) == 0);   // lanes 0 and 16 write y

    for (int t = 0; t < TT; t++) {
        // prefetch next step's xWi (lanes 0..7, 1 LDG/warp)
        float xn = 0.f;
        if (l < 8 && t + 1 < TT) {
            int srcn = (TT - 2 - t + L) & (TT - 1);
            xn = xWib[(size_t)srcn * G4 + gcol];
        }

        // load previous h (own SMEM) as packed pairs
        const unsigned long long* hp =
            (const unsigned long long*)&h_s[t & 1][l * 8];
        unsigned long long h2[4];
        h2[0] = hp[0]; h2[1] = hp[1]; h2[2] = hp[2]; h2[3] = hp[3];

        // 8 packed-f32x2 accumulators (one per gate column)
        unsigned long long acc[8];
#pragma unroll
        for (int j = 0; j < 8; j++) acc[j] = 0ull;
#pragma unroll
        for (int dd = 0; dd < 4; dd++)
#pragma unroll
            for (int j = 0; j < 8; j++)
                asm("fma.rn.f32x2 %0, %1, %2, %0;"
                    : "+l"(acc[j]) : "l"(h2[dd]), "l"(wh2[j][dd]));

        // horizontal pair-sum -> ps[8]
        float ps[8];
#pragma unroll
        for (int j = 0; j < 8; j++) {
            float lo, hi;
            asm("mov.b64 {%0, %1}, %2;" : "=f"(lo), "=f"(hi) : "l"(acc[j]));
            ps[j] = lo + hi;
        }

        // full-split butterfly: 16 SHFL, 5 levels -> quad q holds column q
        float u0, u1, u2, u3;
        {
            float a0 = __shfl_xor_sync(0xffffffffu, ps[0], 16);
            float a4 = __shfl_xor_sync(0xffffffffu, ps[4], 16);
            float a1 = __shfl_xor_sync(0xffffffffu, ps[1], 16);
            float a5 = __shfl_xor_sync(0xffffffffu, ps[5], 16);
            float a2 = __shfl_xor_sync(0xffffffffu, ps[2], 16);
            float a6 = __shfl_xor_sync(0xffffffffu, ps[6], 16);
            float a3 = __shfl_xor_sync(0xffffffffu, ps[3], 16);
            float a7 = __shfl_xor_sync(0xffffffffu, ps[7], 16);
            bool hi = (l & 16);
            u0 = hi ? (ps[4] + a4) : (ps[0] + a0);
            u1 = hi ? (ps[5] + a5) : (ps[1] + a1);
            u2 = hi ? (ps[6] + a6) : (ps[2] + a2);
            u3 = hi ? (ps[7] + a7) : (ps[3] + a3);
        }
        float t0, t1;
        {
            float a0 = __shfl_xor_sync(0xffffffffu, u0, 8);
            float a2 = __shfl_xor_sync(0xffffffffu, u2, 8);
            float a1 = __shfl_xor_sync(0xffffffffu, u1, 8);
            float a3 = __shfl_xor_sync(0xffffffffu, u3, 8);
            bool hi = (l & 8);
            t0 = hi ? (u2 + a2) : (u0 + a0);
            t1 = hi ? (u3 + a3) : (u1 + a1);
        }
        float s;
        {
            float a0 = __shfl_xor_sync(0xffffffffu, t0, 4);
            float a1 = __shfl_xor_sync(0xffffffffu, t1, 4);
            s = (l & 4) ? (t1 + a1) : (t0 + a0);
        }
        s += __shfl_xor_sync(0xffffffffu, s, 2);
        s += __shfl_xor_sync(0xffffffffu, s, 1);

        // add xWi pre-activation (route from loader lane = my quad index)
        float xq = __shfl_sync(0xffffffffu, xc, (l >> 2) & 7);
        s += xq;

        // distributed activation of MY column: sigmoid for i,f,o; tanh for g
        float arg = is_g ? (2.f * s) : s;
        float e   = __expf(-arg);
        float sg  = __fdividef(1.f, 1.f + e);
        float act = is_g ? fmaf(2.f, sg, -1.f) : sg;

        // gather activated gates of my half's h-index (base 0 -> k0, 16 -> k0+1)
        float g0 = __shfl_sync(0xffffffffu, act, base + 0);
        float g1 = __shfl_sync(0xffffffffu, act, base + 4);
        float g2 = __shfl_sync(0xffffffffu, act, base + 8);
        float g3 = __shfl_sync(0xffffffffu, act, base + 12);

        // all lanes: LSTM cell update for their half (redundant, branch-free)
        c_state = fmaf(g1, c_state, g0 * g2);
        float e2 = __expf(-2.f * c_state);
        float tc = fmaf(2.f, __fdividef(1.f, 1.f + e2), -1.f);
        float nh = g3 * tc;

        // other half's nh (k0+1 for lanes 0-15) for the paired v2 store
        float nho = __shfl_sync(0xffffffffu, nh, l | 16);

        // exchange: lanes 0-7 store (nh_k0, nh_k1) to peer p — one SASS
        // instruction for all 16 values. Never on the last step.
        if (t < TT - 1 && l < 8) {
            unsigned int dst =
                st_peer + (((t + 1) & 1) ? (unsigned)HH * 4u : 0u);
            asm volatile("st.shared::cluster.v2.f32 [%0], {%1, %2};"
                         :: "r"(dst), "f"(nh), "f"(nho) : "memory");
        }

        if (t < TT - 1)
            asm volatile("barrier.cluster.arrive.aligned;" ::: "memory");

        // inside the barrier window: y store + register swap
        if (ystore) {
            const int src = (TT - 1 - t + L) & (TT - 1);
            yb[(size_t)src * HH + myk] = nh;
        }
        xc = xn;

        if (t < TT - 1)
            asm volatile("barrier.cluster.wait.aligned;" ::: "memory");
    }
}

// ---------------------------------------------------------------------------
extern "C" void kernel_launch(void* const* d_in, const int* in_sizes, int n_in,
                              void* d_out, int out_size) {
    const float* x    = (const float*)d_in[0];
    const float* Wi   = (const float*)d_in[1];
    const float* Wh   = (const float*)d_in[2];
    const float* bias = (const float*)d_in[3];
    const int*   seql = (const int*)d_in[4];
    float*       y    = (float*)d_out;

    gemm_kernel<<<dim3(G4 / 128, (BB * TT) / 128), 256>>>(x, Wi, bias);
    rnn_kernel<<<BB * CLUS, NTHR>>>(Wh, seql, y);
}